// round 1
// baseline (speedup 1.0000x reference)
#include <cuda_runtime.h>
#include <math.h>

#define N_MET 250000
#define N_RXN 500000
#define E_SUB 2000000
#define E_ALL 4000000
#define DT    0.01f
#define NB1   489   /* ceil(N_RXN/1024) */

// ---------------- constant weights ----------------
__constant__ float cW1[128];   // [2][64] row-major: cW1[j]=W1[0][j], cW1[64+j]=W1[1][j]
__constant__ float cb1[64];
__constant__ float cW2[2048];  // [64][32]
__constant__ float cb2[32];
__constant__ float cW3[2048];  // [32][64]
__constant__ float cb3[64];
__constant__ float cW4[64];
__constant__ float cb4c[1];

// ---------------- device scratch ----------------
__device__ float g_conc[N_MET];
__device__ float g_total[N_MET];
__device__ float g_met_scale[N_MET];
__device__ int   g_count[N_RXN];
__device__ int   g_offset[N_RXN + 1];
__device__ int   g_cursor[N_RXN];
__device__ int   g_bsum[NB1];
__device__ int   g_bofs[NB1];
__device__ float g_perm_c[E_SUB];
__device__ float g_perm_s[E_SUB];
__device__ int   g_perm_met[E_SUB];
__device__ float g_v[N_RXN];

__device__ __forceinline__ float tanh1(float x) {
    float e = __expf(2.0f * x);                 // x->+inf: e=inf -> 1 ; x->-inf: e=0 -> -1
    return 1.0f - __fdividef(2.0f, e + 1.0f);
}

// ---------------- init ----------------
__global__ void k_init(const float* __restrict__ x, float* __restrict__ out) {
    int i = blockIdx.x * blockDim.x + threadIdx.x;
    if (i < N_MET) {
        g_conc[i]  = x[i * 8 + 3];
        g_total[i] = 0.0f;
        out[i]     = 0.0f;
    }
    if (i < N_RXN) {
        g_count[i] = 0;
    }
}

// ---------------- CSR build ----------------
__global__ void k_hist(const int* __restrict__ rxn_sub) {
    int e = blockIdx.x * blockDim.x + threadIdx.x;
    if (e < E_SUB) atomicAdd(&g_count[rxn_sub[e]], 1);
}

__global__ void k_scan_partial() {
    __shared__ int sh[1024];
    int t = threadIdx.x;
    int i = blockIdx.x * 1024 + t;
    sh[t] = (i < N_RXN) ? g_count[i] : 0;
    __syncthreads();
    for (int s = 512; s > 0; s >>= 1) {
        if (t < s) sh[t] += sh[t + s];
        __syncthreads();
    }
    if (t == 0) g_bsum[blockIdx.x] = sh[0];
}

__global__ void k_scan_bsum() {
    __shared__ int sh[512];
    int t = threadIdx.x;
    int vorig = (t < NB1) ? g_bsum[t] : 0;
    sh[t] = vorig;
    __syncthreads();
    for (int off = 1; off < 512; off <<= 1) {
        int add = (t >= off) ? sh[t - off] : 0;
        __syncthreads();
        sh[t] += add;
        __syncthreads();
    }
    if (t < NB1) g_bofs[t] = sh[t] - vorig;
}

__global__ void k_scan_final() {
    __shared__ int sh[1024];
    int t = threadIdx.x;
    int i = blockIdx.x * 1024 + t;
    int c = (i < N_RXN) ? g_count[i] : 0;
    sh[t] = c;
    __syncthreads();
    for (int off = 1; off < 1024; off <<= 1) {
        int add = (t >= off) ? sh[t - off] : 0;
        __syncthreads();
        sh[t] += add;
        __syncthreads();
    }
    if (i < N_RXN) {
        int base = g_bofs[blockIdx.x];
        int excl = base + sh[t] - c;
        g_offset[i] = excl;
        g_cursor[i] = excl;
        if (i == N_RXN - 1) g_offset[N_RXN] = base + sh[t];
    }
}

__global__ void k_scatter(const int* __restrict__ met_sub,
                          const int* __restrict__ rxn_sub,
                          const float* __restrict__ sto_sub) {
    int e = blockIdx.x * blockDim.x + threadIdx.x;
    if (e >= E_SUB) return;
    int r = rxn_sub[e];
    int m = met_sub[e];
    int p = atomicAdd(&g_cursor[r], 1);
    g_perm_c[p]   = g_conc[m];
    g_perm_s[p]   = sto_sub[e];
    g_perm_met[p] = m;
}

// ---------------- fused per-reaction MLP ----------------
__global__ void __launch_bounds__(256) k_rxn(const float* __restrict__ log_k) {
    int r = blockIdx.x * blockDim.x + threadIdx.x;
    if (r >= N_RXN) return;
    int beg = g_offset[r];
    int end = g_offset[r + 1];
    float n = (float)(end - beg);

    float h[32];
#pragma unroll
    for (int k = 0; k < 32; k++) h[k] = 0.0f;

    // hidden dim in 8 chunks of 8: T regs stay statically indexed
    for (int jc = 0; jc < 8; ++jc) {
        float T[8];
#pragma unroll
        for (int j = 0; j < 8; j++) T[j] = 0.0f;
        for (int i = beg; i < end; ++i) {
            float c = g_perm_c[i];
            float s = g_perm_s[i];
#pragma unroll
            for (int j = 0; j < 8; j++) {
                int jj = jc * 8 + j;
                float z = fmaf(c, cW1[jj], fmaf(s, cW1[64 + jj], cb1[jj]));
                T[j] += tanh1(z);
            }
        }
#pragma unroll
        for (int j = 0; j < 8; j++) {
            float t = T[j];
            int jj = jc * 8 + j;
#pragma unroll
            for (int k = 0; k < 32; k++) h[k] = fmaf(t, cW2[jj * 32 + k], h[k]);
        }
    }
#pragma unroll
    for (int k = 0; k < 32; k++) h[k] = fmaf(n, cb2[k], h[k]);

    float racc = cb4c[0];
    for (int j = 0; j < 64; ++j) {
        float a = cb3[j];
#pragma unroll
        for (int k = 0; k < 32; k++) a = fmaf(h[k], cW3[k * 64 + j], a);
        racc = fmaf(tanh1(a), cW4[j], racc);
    }

    // v = 10^log_k * softplus(racc)
    float sp = fmaxf(racc, 0.0f) + log1pf(__expf(-fabsf(racc)));
    float kk = __expf(log_k[r] * 2.302585093f);
    g_v[r] = kk * sp;
}

// ---------------- consumption -> total (per-met) ----------------
__global__ void k_total(const int* __restrict__ met_sub,
                        const int* __restrict__ rxn_sub,
                        const float* __restrict__ sto_sub) {
    int e = blockIdx.x * blockDim.x + threadIdx.x;
    if (e >= E_SUB) return;
    float cons = sto_sub[e] * g_v[rxn_sub[e]] * DT;
    atomicAdd(&g_total[met_sub[e]], cons);
}

__global__ void k_metscale() {
    int i = blockIdx.x * blockDim.x + threadIdx.x;
    if (i >= N_MET) return;
    float t = g_total[i];
    float c = g_conc[i];
    g_met_scale[i] = (t > 1e-12f) ? fminf(c / t, 1.0f) : 1.0f;
}

// rxn_scale = min over this rxn's edges of met_scale (CSR gather, no atomics)
__global__ void k_vscale() {
    int r = blockIdx.x * blockDim.x + threadIdx.x;
    if (r >= N_RXN) return;
    int beg = g_offset[r];
    int end = g_offset[r + 1];
    float m = 1.0f;
    for (int i = beg; i < end; ++i) m = fminf(m, g_met_scale[g_perm_met[i]]);
    g_v[r] *= m;
}

// ---------------- final scatter into dxdt ----------------
__global__ void k_out(const int* __restrict__ met_all,
                      const int* __restrict__ rxn_all,
                      const float* __restrict__ sto_all,
                      float* __restrict__ out) {
    int e = blockIdx.x * blockDim.x + threadIdx.x;
    if (e >= E_ALL) return;
    float contrib = sto_all[e] * g_v[rxn_all[e]];
    atomicAdd(&out[met_all[e]], contrib);
}

extern "C" void kernel_launch(void* const* d_in, const int* in_sizes, int n_in,
                              void* d_out, int out_size) {
    const float* x       = (const float*)d_in[0];
    const int*   met_sub = (const int*)d_in[1];
    const int*   rxn_sub = (const int*)d_in[2];
    const float* sto_sub = (const float*)d_in[3];
    const int*   met_all = (const int*)d_in[4];
    const int*   rxn_all = (const int*)d_in[5];
    const float* sto_all = (const float*)d_in[6];
    const float* log_k   = (const float*)d_in[15];
    float* out = (float*)d_out;

    cudaMemcpyToSymbolAsync(cW1,  d_in[7],  128  * sizeof(float), 0, cudaMemcpyDeviceToDevice, 0);
    cudaMemcpyToSymbolAsync(cb1,  d_in[8],  64   * sizeof(float), 0, cudaMemcpyDeviceToDevice, 0);
    cudaMemcpyToSymbolAsync(cW2,  d_in[9],  2048 * sizeof(float), 0, cudaMemcpyDeviceToDevice, 0);
    cudaMemcpyToSymbolAsync(cb2,  d_in[10], 32   * sizeof(float), 0, cudaMemcpyDeviceToDevice, 0);
    cudaMemcpyToSymbolAsync(cW3,  d_in[11], 2048 * sizeof(float), 0, cudaMemcpyDeviceToDevice, 0);
    cudaMemcpyToSymbolAsync(cb3,  d_in[12], 64   * sizeof(float), 0, cudaMemcpyDeviceToDevice, 0);
    cudaMemcpyToSymbolAsync(cW4,  d_in[13], 64   * sizeof(float), 0, cudaMemcpyDeviceToDevice, 0);
    cudaMemcpyToSymbolAsync(cb4c, d_in[14], 1    * sizeof(float), 0, cudaMemcpyDeviceToDevice, 0);

    k_init<<<(N_RXN + 255) / 256, 256>>>(x, out);
    k_hist<<<(E_SUB + 255) / 256, 256>>>(rxn_sub);
    k_scan_partial<<<NB1, 1024>>>();
    k_scan_bsum<<<1, 512>>>();
    k_scan_final<<<NB1, 1024>>>();
    k_scatter<<<(E_SUB + 255) / 256, 256>>>(met_sub, rxn_sub, sto_sub);
    k_rxn<<<(N_RXN + 255) / 256, 256>>>(log_k);
    k_total<<<(E_SUB + 255) / 256, 256>>>(met_sub, rxn_sub, sto_sub);
    k_metscale<<<(N_MET + 255) / 256, 256>>>();
    k_vscale<<<(N_RXN + 255) / 256, 256>>>();
    k_out<<<(E_ALL + 255) / 256, 256>>>(met_all, rxn_all, sto_all, out);
}